// round 3
// baseline (speedup 1.0000x reference)
#include <cuda_runtime.h>
#include <cstdint>

#define N_POINTS_C 1048576
#define N_LEVELS_C 16
#define LOG2_T_C 19
#define T_C (1u << LOG2_T_C)
#define TMASK_C (T_C - 1u)

#define NBUCKETS 32768   // 32^3 spatial buckets, ~32 points each

__constant__ int c_res[N_LEVELS_C] = {
    16, 20, 25, 32, 40, 50, 64, 80, 101, 128, 161, 203, 256, 322, 406, 512
};

// Scratch (device globals: allocation-free).
__device__ unsigned int g_hist[NBUCKETS];
__device__ unsigned int g_offs[NBUCKETS];
__device__ float4       g_xs[N_POINTS_C];   // sorted (x,y,z, orig-idx-bits)

__device__ __forceinline__ int bucket_of(float px, float py, float pz) {
    int bx = (int)(px * 32.0f); bx = bx > 31 ? 31 : (bx < 0 ? 0 : bx);
    int by = (int)(py * 32.0f); by = by > 31 ? 31 : (by < 0 ? 0 : by);
    int bz = (int)(pz * 32.0f); bz = bz > 31 ? 31 : (bz < 0 ? 0 : bz);
    return (bz << 10) | (by << 5) | bx;
}

__global__ void zero_hist_kernel() {
    int i = blockIdx.x * blockDim.x + threadIdx.x;
    if (i < NBUCKETS) g_hist[i] = 0u;
}

__global__ void hist_kernel(const float* __restrict__ x) {
    int n = blockIdx.x * blockDim.x + threadIdx.x;
    if (n >= N_POINTS_C) return;
    float px = x[3 * n + 0], py = x[3 * n + 1], pz = x[3 * n + 2];
    atomicAdd(&g_hist[bucket_of(px, py, pz)], 1u);
}

// Exclusive prefix sum over 32768 bins: 1 block of 1024 threads, 32 bins each.
__global__ void scan_kernel() {
    __shared__ unsigned int part[1024];
    const int t = threadIdx.x;
    unsigned int local[32];
    unsigned int s = 0;
#pragma unroll
    for (int j = 0; j < 32; j++) {
        local[j] = s;
        s += g_hist[t * 32 + j];
    }
    part[t] = s;
    __syncthreads();
    for (int d = 1; d < 1024; d <<= 1) {
        unsigned int v = part[t];
        unsigned int add = (t >= d) ? part[t - d] : 0u;
        __syncthreads();
        part[t] = v + add;
        __syncthreads();
    }
    unsigned int base = (t == 0) ? 0u : part[t - 1];
#pragma unroll
    for (int j = 0; j < 32; j++)
        g_offs[t * 32 + j] = base + local[j];
}

__global__ void scatter_kernel(const float* __restrict__ x) {
    int n = blockIdx.x * blockDim.x + threadIdx.x;
    if (n >= N_POINTS_C) return;
    float px = x[3 * n + 0], py = x[3 * n + 1], pz = x[3 * n + 2];
    int b = bucket_of(px, py, pz);
    unsigned int pos = atomicAdd(&g_offs[b], 1u);
    g_xs[pos] = make_float4(px, py, pz, __int_as_float(n));
}

__global__ void __launch_bounds__(256, 5) hashgrid_kernel(
    const float* __restrict__ emb,
    float* __restrict__ out)
{
    const int n = blockIdx.x * blockDim.x + threadIdx.x;
    if (n >= N_POINTS_C) return;

    const float4 p = g_xs[n];
    const float px = p.x, py = p.y, pz = p.z;
    const int  oidx = __float_as_int(p.w);

    float acc[2 * N_LEVELS_C];

#pragma unroll
    for (int l = 0; l < N_LEVELS_C; l++) {
        const int res = c_res[l];
        const float rf = (float)(res - 1);

        const float sx = px * rf;
        const float sy = py * rf;
        const float sz = pz * rf;

        int fx = (int)sx; fx = fx > res - 2 ? res - 2 : fx; fx = fx < 0 ? 0 : fx;
        int fy = (int)sy; fy = fy > res - 2 ? res - 2 : fy; fy = fy < 0 ? 0 : fy;
        int fz = (int)sz; fz = fz > res - 2 ? res - 2 : fz; fz = fz < 0 ? 0 : fz;

        const float tx = sx - (float)fx;
        const float ty = sy - (float)fy;
        const float tz = sz - (float)fz;
        const float ux = 1.0f - tx;
        const float uy = 1.0f - ty;
        const float uz = 1.0f - tz;

        // y/z hash components
        const unsigned hy0 = (unsigned)fy * 2654435761u;
        const unsigned hy1 = hy0 + 2654435761u;
        const unsigned hz0 = (unsigned)fz * 805459861u;
        const unsigned hz1 = hz0 + 805459861u;

        // 4 (y,z) XOR masks
        unsigned mm[4];
        mm[0] = hy0 ^ hz0;
        mm[1] = hy1 ^ hz0;
        mm[2] = hy0 ^ hz1;
        mm[3] = hy1 ^ hz1;

        // x-pair trick: for even base e = fx & ~1, entries h(e) and
        // h(e+1) = h(e)^1 form one aligned float4. Odd lanes additionally
        // fetch h(e+2) (= h(fx+1)) with a predicated float2 load.
        const unsigned e  = (unsigned)(fx & ~1);
        const bool     odd = (fx & 1) != 0;

        const float2* __restrict__ tab =
            reinterpret_cast<const float2*>(emb) + (size_t)l * T_C;
        const float4* __restrict__ tab4 =
            reinterpret_cast<const float4*>(tab);

        unsigned he[4], h2[4];
#pragma unroll
        for (int c = 0; c < 4; c++) {
            he[c] = (e ^ mm[c]) & TMASK_C;
            h2[c] = ((e + 2u) ^ mm[c]) & TMASK_C;
        }

        float4 q[4];
#pragma unroll
        for (int c = 0; c < 4; c++) q[c] = __ldg(&tab4[he[c] >> 1]);

        float2 v2[4];
#pragma unroll
        for (int c = 0; c < 4; c++) {
            v2[c] = make_float2(0.0f, 0.0f);
            if (odd) v2[c] = __ldg(&tab[h2[c]]);
        }

        // weights: pair c -> (y,z) factor; x factor is ux/tx
        float wyz[4];
        wyz[0] = uy * uz;
        wyz[1] = ty * uz;
        wyz[2] = uy * tz;
        wyz[3] = ty * tz;

        float a0 = 0.0f, a1 = 0.0f;
#pragma unroll
        for (int c = 0; c < 4; c++) {
            // entries of q[c]: low = he&~1, high = he|1
            // v(e)   has hash he[c]
            // v(e+1) has hash he[c]^1
            float2 ve, ve1;
            if (he[c] & 1u) {
                ve  = make_float2(q[c].z, q[c].w);
                ve1 = make_float2(q[c].x, q[c].y);
            } else {
                ve  = make_float2(q[c].x, q[c].y);
                ve1 = make_float2(q[c].z, q[c].w);
            }
            // corner (fx) and corner (fx+1)
            float2 vx0 = odd ? ve1 : ve;
            float2 vx1 = odd ? v2[c] : ve1;

            const float w0 = ux * wyz[c];
            const float w1 = tx * wyz[c];
            a0 += w0 * vx0.x + w1 * vx1.x;
            a1 += w0 * vx0.y + w1 * vx1.y;
        }
        acc[2 * l + 0] = a0;
        acc[2 * l + 1] = a1;
    }

    float4* __restrict__ o = reinterpret_cast<float4*>(out + (size_t)oidx * 32);
#pragma unroll
    for (int i = 0; i < 8; i++) {
        o[i] = make_float4(acc[4 * i + 0], acc[4 * i + 1],
                           acc[4 * i + 2], acc[4 * i + 3]);
    }
}

extern "C" void kernel_launch(void* const* d_in, const int* in_sizes, int n_in,
                              void* d_out, int out_size)
{
    const float* x = (const float*)d_in[0];
    const float* emb = (const float*)d_in[1];
    float* out = (float*)d_out;

    const int threads = 256;
    const int pblocks = (N_POINTS_C + threads - 1) / threads;

    zero_hist_kernel<<<(NBUCKETS + 255) / 256, 256>>>();
    hist_kernel<<<pblocks, threads>>>(x);
    scan_kernel<<<1, 1024>>>();
    scatter_kernel<<<pblocks, threads>>>(x);
    hashgrid_kernel<<<pblocks, threads>>>(emb, out);
}